// round 10
// baseline (speedup 1.0000x reference)
#include <cuda_runtime.h>
#include <math.h>

#define SOM_DIM   512
#define SOM_MN    65536              // 256*256 rows
#define NBLK      148                // one CTA per SM, all resident (GB300 has 152)
#define NTHR      1024
#define NWARP     32
#define STASH_ROWS 108               // 108 rows * 2KB = 221184 B dynamic SMEM
#define STASH_BYTES (STASH_ROWS * SOM_DIM * 4)

// Row partition: first 120 blocks get 443 rows, remaining 28 get 442.
// 120*443 + 28*442 = 65536.
#define BIG_BLOCKS 120
#define ROWS_BIG   443
#define ROWS_SMALL 442

__device__ unsigned long long g_key = 0xFFFFFFFFFFFFFFFFULL;
__device__ unsigned int g_done1 = 0;
__device__ unsigned int g_done2 = 0;
__device__ unsigned int g_flag  = 0;
__device__ float g_sc[4];            // rate, inv2s2, b0, b1

__device__ __forceinline__ void stg_cs(float4* p, float4 v) {
    asm volatile("st.global.cs.v4.f32 [%0], {%1,%2,%3,%4};"
                 :: "l"(p), "f"(v.x), "f"(v.y), "f"(v.z), "f"(v.w) : "memory");
}

// ---------------------------------------------------------------------------
// Fused SOM kernel: phase 1 (distance+argmin, stash W front rows in SMEM),
// grid-wide flag sync (all NBLK CTAs resident => no deadlock),
// phase 2 (weight update, reverse order: L2-fresh tail first, SMEM last).
// ---------------------------------------------------------------------------
__global__ __launch_bounds__(NTHR, 1) void som_fused_kernel(
    const float* __restrict__ x, const float* __restrict__ w,
    const float* __restrict__ loc, const int* __restrict__ it_p,
    float* __restrict__ out, int has_idx_tail)
{
    extern __shared__ float4 stash[];            // [STASH_ROWS][128]
    __shared__ unsigned long long s_keys[NWARP];
    __shared__ float s_sc[4];

    const int tid  = threadIdx.x;
    const int lane = tid & 31;
    const int warp = tid >> 5;
    const int b    = blockIdx.x;

    const int start = (b < BIG_BLOCKS) ? b * ROWS_BIG
                                       : BIG_BLOCKS * ROWS_BIG + (b - BIG_BLOCKS) * ROWS_SMALL;
    const int nrows = (b < BIG_BLOCKS) ? ROWS_BIG : ROWS_SMALL;
    const int iters = (nrows + NWARP - 1) / NWARP;   // 14

    // x resident in registers for both phases.
    const float4* __restrict__ xr = (const float4*)x;
    float4 xv[4];
#pragma unroll
    for (int i = 0; i < 4; i++) xv[i] = __ldg(&xr[lane + 32 * i]);

    // ---------------- Phase 1: distances + stash ----------------
    unsigned long long mykey = 0xFFFFFFFFFFFFFFFFULL;
    for (int itn = 0; itn < iters; itn++) {
        const int rl = itn * NWARP + warp;
        if (rl < nrows) {
            const int row = start + rl;
            const float4* __restrict__ wr = (const float4*)(w + (size_t)row * SOM_DIM);
            float4 wv[4];
#pragma unroll
            for (int i = 0; i < 4; i++) wv[i] = wr[lane + 32 * i];
            if (rl < STASH_ROWS) {
#pragma unroll
                for (int i = 0; i < 4; i++)
                    stash[rl * 128 + lane + 32 * i] = wv[i];
            }
            float a = 0.f;
#pragma unroll
            for (int i = 0; i < 4; i++) {
                float d;
                d = xv[i].x - wv[i].x + 1e-6f; a += d * d;
                d = xv[i].y - wv[i].y + 1e-6f; a += d * d;
                d = xv[i].z - wv[i].z + 1e-6f; a += d * d;
                d = xv[i].w - wv[i].w + 1e-6f; a += d * d;
            }
#pragma unroll
            for (int o = 16; o > 0; o >>= 1)
                a += __shfl_xor_sync(0xFFFFFFFFu, a, o);
            if (lane == 0) {
                // dist >= 0: fp32 bits order-preserving; low bits = row for
                // first-occurrence tie-break (matches jnp.argmin).
                unsigned long long k =
                    ((unsigned long long)__float_as_uint(a) << 32) | (unsigned)row;
                mykey = min(mykey, k);
            }
        }
    }
    if (lane == 0) s_keys[warp] = mykey;
    __syncthreads();

    // ---------------- Grid sync + scalar broadcast ----------------
    if (tid == 0) {
        unsigned long long k = s_keys[0];
#pragma unroll
        for (int i = 1; i < NWARP; i++) k = min(k, s_keys[i]);
        atomicMin(&g_key, k);

        __threadfence();
        const unsigned t = atomicAdd(&g_done1, 1u);
        if (t == (unsigned)(NBLK - 1)) {
            g_done1 = 0u;
            const int bidx = (int)(g_key & 0xFFFFFFFFu);
            g_key = 0xFFFFFFFFFFFFFFFFULL;           // reset for next replay
            const int it   = *it_p;
            const float decay = expf(-(float)it / 2000.0f);  // N_ITER
            const float sig   = 128.0f * decay;              // SIGMA * decay
            g_sc[0] = 0.5f * decay;                          // ALPHA * decay
            g_sc[1] = 1.0f / (2.0f * sig * sig);
            g_sc[2] = loc[2 * bidx];
            g_sc[3] = loc[2 * bidx + 1];
            if (has_idx_tail)
                out[(size_t)SOM_MN * SOM_DIM] = (float)bidx;
            __threadfence();
            atomicExch(&g_flag, 1u);                 // release
        }
        // Everyone (including the releasing block) acquires the flag.
        unsigned f;
        do {
            asm volatile("ld.acquire.gpu.global.u32 %0, [%1];"
                         : "=r"(f) : "l"(&g_flag));
            if (!f) __nanosleep(128);
        } while (!f);
        s_sc[0] = g_sc[0]; s_sc[1] = g_sc[1];
        s_sc[2] = g_sc[2]; s_sc[3] = g_sc[3];
    }
    __syncthreads();

    const float rate   = s_sc[0];
    const float inv2s2 = s_sc[1];
    const float b0     = s_sc[2];
    const float b1     = s_sc[3];

    // ---------------- Phase 2: update, reverse order ----------------
    for (int itn = iters - 1; itn >= 0; itn--) {
        const int rl = itn * NWARP + warp;
        if (rl < nrows) {
            const int row = start + rl;
            float4 wv[4];
            if (rl < STASH_ROWS) {
#pragma unroll
                for (int i = 0; i < 4; i++)
                    wv[i] = stash[rl * 128 + lane + 32 * i];
            } else {
                const float4* __restrict__ wr = (const float4*)(w + (size_t)row * SOM_DIM);
#pragma unroll
                for (int i = 0; i < 4; i++) wv[i] = wr[lane + 32 * i];
            }
            const float d0 = b0 - __ldg(&loc[2 * row])     + 1e-6f;
            const float d1 = b1 - __ldg(&loc[2 * row + 1]) + 1e-6f;
            const float ld = sqrtf(d0 * d0 + d1 * d1);   // match sqrt-then-square
            const float c  = rate * expf(-(ld * ld) * inv2s2);

            float4* __restrict__ orow = (float4*)(out + (size_t)row * SOM_DIM);
#pragma unroll
            for (int i = 0; i < 4; i++) {
                float4 o;
                o.x = wv[i].x + c * (xv[i].x - wv[i].x);
                o.y = wv[i].y + c * (xv[i].y - wv[i].y);
                o.z = wv[i].z + c * (xv[i].z - wv[i].z);
                o.w = wv[i].w + c * (xv[i].w - wv[i].w);
                stg_cs(&orow[lane + 32 * i], o);
            }
        }
    }

    // ---------------- Reset flag for next graph replay ----------------
    __syncthreads();
    if (tid == 0) {
        const unsigned t = atomicAdd(&g_done2, 1u);
        if (t == (unsigned)(NBLK - 1)) {
            g_done2 = 0u;
            atomicExch(&g_flag, 0u);
        }
    }
}

extern "C" void kernel_launch(void* const* d_in, const int* in_sizes, int n_in,
                              void* d_out, int out_size)
{
    const float* x   = (const float*)d_in[0];   // (512,)
    const float* w   = (const float*)d_in[1];   // (65536, 512)
    const float* loc = (const float*)d_in[2];   // (65536, 2)
    const int*   it  = (const int*)d_in[3];     // scalar
    float* out = (float*)d_out;

    const int has_tail = (out_size > SOM_MN * SOM_DIM) ? 1 : 0;

    cudaFuncSetAttribute(som_fused_kernel,
                         cudaFuncAttributeMaxDynamicSharedMemorySize, STASH_BYTES);
    som_fused_kernel<<<NBLK, NTHR, STASH_BYTES>>>(x, w, loc, it, out, has_tail);
}

// round 11
// speedup vs baseline: 1.0685x; 1.0685x over previous
#include <cuda_runtime.h>
#include <math.h>

#define SOM_DIM   512
#define SOM_MN    65536            // 256*256 rows
#define ROW_SPLIT 36864            // rows >= this (57MB tail) pinned evict-last in L2

// Pass 1: 2 rows per warp, 8 warps/block.
#define P1_WARPS 8
#define P1_ROWS_PER_BLK (P1_WARPS * 2)            // 16
#define P1_BLOCKS (SOM_MN / P1_ROWS_PER_BLK)      // 4096

// Pass 2: 1 row per warp, 8 warps/block.
#define P2_ROWS_PER_BLK 8
#define P2_BLOCKS (SOM_MN / P2_ROWS_PER_BLK)      // 8192

__device__ unsigned long long g_key = 0xFFFFFFFFFFFFFFFFULL;
__device__ unsigned int g_ticket1 = 0;
__device__ unsigned int g_ticket2 = 0;
__device__ float g_rate;
__device__ float g_inv2s2;
__device__ float g_b0;
__device__ float g_b1;

// ---- L2 cache-policy helpers ------------------------------------------------
__device__ __forceinline__ unsigned long long pol_evict_last() {
    unsigned long long p;
    asm("createpolicy.fractional.L2::evict_last.b64 %0, 1.0;" : "=l"(p));
    return p;
}
__device__ __forceinline__ unsigned long long pol_evict_first() {
    unsigned long long p;
    asm("createpolicy.fractional.L2::evict_first.b64 %0, 1.0;" : "=l"(p));
    return p;
}
__device__ __forceinline__ float4 ldg_pol(const float4* p, unsigned long long pol) {
    float4 v;
    asm("ld.global.L2::cache_hint.v4.f32 {%0,%1,%2,%3}, [%4], %5;"
        : "=f"(v.x), "=f"(v.y), "=f"(v.z), "=f"(v.w) : "l"(p), "l"(pol));
    return v;
}

// ---------------------------------------------------------------------------
// Pass 1: squared distance per row (argmin of sqrt == argmin of sum).
// 2 rows per warp. W tail rows (>= ROW_SPLIT, 57MB) loaded evict-last —
// sized under the observed ~59MB retention cap so the pinned set does not
// thrash itself; head rows evict-first. Block min -> atomicMin(g_key);
// last-finishing block computes iteration scalars + bmu tail write.
// ---------------------------------------------------------------------------
__global__ __launch_bounds__(256) void som_dist_kernel(
    const float* __restrict__ x, const float* __restrict__ w,
    const float* __restrict__ loc, const int* __restrict__ it_p,
    float* __restrict__ out, int has_idx_tail)
{
    __shared__ unsigned long long s_keys[P1_WARPS];
    const int lane = threadIdx.x & 31;
    const int warp = threadIdx.x >> 5;
    const int row0 = blockIdx.x * P1_ROWS_PER_BLK + warp * 2;

    const unsigned long long pol = (row0 >= ROW_SPLIT) ? pol_evict_last()
                                                       : pol_evict_first();

    const float4* __restrict__ xr  = (const float4*)x;
    const float4* __restrict__ wr0 = (const float4*)(w + (size_t)row0 * SOM_DIM);
    const float4* __restrict__ wr1 = (const float4*)(w + (size_t)(row0 + 1) * SOM_DIM);

    float4 wv0[4], wv1[4], xv[4];
#pragma unroll
    for (int i = 0; i < 4; i++) wv0[i] = ldg_pol(&wr0[lane + 32 * i], pol);
#pragma unroll
    for (int i = 0; i < 4; i++) wv1[i] = ldg_pol(&wr1[lane + 32 * i], pol);
#pragma unroll
    for (int i = 0; i < 4; i++) xv[i]  = __ldg(&xr[lane + 32 * i]);

    float a0 = 0.f, a1 = 0.f;
#pragma unroll
    for (int i = 0; i < 4; i++) {
        float d;
        d = xv[i].x - wv0[i].x + 1e-6f; a0 += d * d;
        d = xv[i].y - wv0[i].y + 1e-6f; a0 += d * d;
        d = xv[i].z - wv0[i].z + 1e-6f; a0 += d * d;
        d = xv[i].w - wv0[i].w + 1e-6f; a0 += d * d;
        d = xv[i].x - wv1[i].x + 1e-6f; a1 += d * d;
        d = xv[i].y - wv1[i].y + 1e-6f; a1 += d * d;
        d = xv[i].z - wv1[i].z + 1e-6f; a1 += d * d;
        d = xv[i].w - wv1[i].w + 1e-6f; a1 += d * d;
    }
#pragma unroll
    for (int o = 16; o > 0; o >>= 1) {
        a0 += __shfl_xor_sync(0xFFFFFFFFu, a0, o);
        a1 += __shfl_xor_sync(0xFFFFFFFFu, a1, o);
    }

    if (lane == 0) {
        // dist >= 0 so fp32 bits are order-preserving; smaller row wins ties.
        unsigned long long k0 =
            ((unsigned long long)__float_as_uint(a0) << 32) | (unsigned)row0;
        unsigned long long k1 =
            ((unsigned long long)__float_as_uint(a1) << 32) | (unsigned)(row0 + 1);
        s_keys[warp] = min(k0, k1);
    }
    __syncthreads();
    if (threadIdx.x == 0) {
        unsigned long long k = s_keys[0];
#pragma unroll
        for (int i = 1; i < P1_WARPS; i++)
            k = min(k, s_keys[i]);
        atomicMin(&g_key, k);

        __threadfence();
        const unsigned t = atomicAdd(&g_ticket1, 1u);
        if (t == (unsigned)(gridDim.x - 1)) {
            g_ticket1 = 0u;
            const int bidx = (int)(g_key & 0xFFFFFFFFu);
            const int it   = *it_p;
            const float decay = expf(-(float)it / 2000.0f);   // N_ITER
            const float sig   = 128.0f * decay;               // SIGMA * decay
            g_rate   = 0.5f * decay;                          // ALPHA * decay
            g_inv2s2 = 1.0f / (2.0f * sig * sig);
            g_b0 = loc[2 * bidx];
            g_b1 = loc[2 * bidx + 1];
            if (has_idx_tail)
                out[(size_t)SOM_MN * SOM_DIM] = (float)bidx;
            __threadfence();
        }
    }
}

// ---------------------------------------------------------------------------
// Pass 2: 1 row per warp, DESCENDING rows (pinned tail first — L2 hits).
// Tail W re-read evict-last (keeps residency for next replay); head rows
// evict-first. Out stored .cs. __launch_bounds__(256,6) caps regs at 40
// to lift occupancy ~50% -> ~75%.
// ---------------------------------------------------------------------------
__global__ __launch_bounds__(256, 6) void som_update_kernel(
    const float* __restrict__ x, const float* __restrict__ w,
    const float* __restrict__ loc, float* __restrict__ out)
{
    const int lane = threadIdx.x & 31;
    const int warp = threadIdx.x >> 5;
    const int row  = (SOM_MN - 1) - (blockIdx.x * P2_ROWS_PER_BLK + warp);

    const unsigned long long pol = (row >= ROW_SPLIT) ? pol_evict_last()
                                                      : pol_evict_first();

    const float4* __restrict__ xr = (const float4*)x;
    const float4* __restrict__ wr = (const float4*)(w + (size_t)row * SOM_DIM);
    float4* __restrict__ orow = (float4*)(out + (size_t)row * SOM_DIM);

    // Front-batch all memory (8 independent loads per lane).
    float4 wv[4], xv[4];
#pragma unroll
    for (int i = 0; i < 4; i++) wv[i] = ldg_pol(&wr[lane + 32 * i], pol);
#pragma unroll
    for (int i = 0; i < 4; i++) xv[i] = __ldg(&xr[lane + 32 * i]);

    // Per-row coefficient from precomputed scalars (overlaps load latency).
    const float d0 = g_b0 - __ldg(&loc[2 * row])     + 1e-6f;
    const float d1 = g_b1 - __ldg(&loc[2 * row + 1]) + 1e-6f;
    const float ld = sqrtf(d0 * d0 + d1 * d1);        // match sqrt-then-square
    const float c  = g_rate * expf(-(ld * ld) * g_inv2s2);

#pragma unroll
    for (int i = 0; i < 4; i++) {
        float4 o;
        o.x = wv[i].x + c * (xv[i].x - wv[i].x);
        o.y = wv[i].y + c * (xv[i].y - wv[i].y);
        o.z = wv[i].z + c * (xv[i].z - wv[i].z);
        o.w = wv[i].w + c * (xv[i].w - wv[i].w);
        __stcs(&orow[lane + 32 * i], o);
    }

    // Last finishing block resets g_key for the next graph replay.
    __syncthreads();
    if (threadIdx.x == 0) {
        const unsigned t = atomicAdd(&g_ticket2, 1u);
        if (t == (unsigned)(gridDim.x - 1)) {
            g_ticket2 = 0u;
            g_key = 0xFFFFFFFFFFFFFFFFULL;
            __threadfence();
        }
    }
}

extern "C" void kernel_launch(void* const* d_in, const int* in_sizes, int n_in,
                              void* d_out, int out_size)
{
    const float* x   = (const float*)d_in[0];   // (512,)
    const float* w   = (const float*)d_in[1];   // (65536, 512)
    const float* loc = (const float*)d_in[2];   // (65536, 2)
    const int*   it  = (const int*)d_in[3];     // scalar
    float* out = (float*)d_out;

    const int has_tail = (out_size > SOM_MN * SOM_DIM) ? 1 : 0;

    som_dist_kernel<<<P1_BLOCKS, 256>>>(x, w, loc, it, out, has_tail);
    som_update_kernel<<<P2_BLOCKS, 256>>>(x, w, loc, out);
}

// round 12
// speedup vs baseline: 1.0966x; 1.0264x over previous
#include <cuda_runtime.h>
#include <math.h>

#define SOM_DIM   512
#define SOM_MN    65536            // 256*256 rows
#define ROW_SPLIT 20480            // rows >= this pinned evict-last in L2 (R8 config)

// Pass 1: 2 rows per warp, 8 warps/block.
#define P1_WARPS 8
#define P1_ROWS_PER_BLK (P1_WARPS * 2)            // 16
#define P1_BLOCKS (SOM_MN / P1_ROWS_PER_BLK)      // 4096

// Pass 2: 1 row per warp, 8 warps/block.
#define P2_ROWS_PER_BLK 8
#define P2_BLOCKS (SOM_MN / P2_ROWS_PER_BLK)      // 8192

__device__ unsigned long long g_key = 0xFFFFFFFFFFFFFFFFULL;
__device__ unsigned int g_ticket1 = 0;
__device__ unsigned int g_ticket2 = 0;
__device__ float g_rate;
__device__ float g_inv2s2;
__device__ float g_b0;
__device__ float g_b1;

// ---- L2 cache-policy helpers ------------------------------------------------
__device__ __forceinline__ unsigned long long pol_evict_last() {
    unsigned long long p;
    asm("createpolicy.fractional.L2::evict_last.b64 %0, 1.0;" : "=l"(p));
    return p;
}
__device__ __forceinline__ unsigned long long pol_evict_first() {
    unsigned long long p;
    asm("createpolicy.fractional.L2::evict_first.b64 %0, 1.0;" : "=l"(p));
    return p;
}
__device__ __forceinline__ float4 ldg_pol(const float4* p, unsigned long long pol) {
    float4 v;
    asm("ld.global.L2::cache_hint.v4.f32 {%0,%1,%2,%3}, [%4], %5;"
        : "=f"(v.x), "=f"(v.y), "=f"(v.z), "=f"(v.w) : "l"(p), "l"(pol));
    return v;
}

// ---------------------------------------------------------------------------
// Pass 1: squared distance per row (argmin of sqrt == argmin of sum).
// 2 rows per warp; W tail rows evict-last, head evict-first. Block min ->
// atomicMin(g_key); each block then triggers the PDL completion event so
// pass 2 can start its (p1-independent) load ramp while p1 drains.
// Last-finishing block computes iteration scalars + bmu tail write.
// ---------------------------------------------------------------------------
__global__ __launch_bounds__(256) void som_dist_kernel(
    const float* __restrict__ x, const float* __restrict__ w,
    const float* __restrict__ loc, const int* __restrict__ it_p,
    float* __restrict__ out, int has_idx_tail)
{
    __shared__ unsigned long long s_keys[P1_WARPS];
    const int lane = threadIdx.x & 31;
    const int warp = threadIdx.x >> 5;
    const int row0 = blockIdx.x * P1_ROWS_PER_BLK + warp * 2;

    const unsigned long long pol = (row0 >= ROW_SPLIT) ? pol_evict_last()
                                                       : pol_evict_first();

    const float4* __restrict__ xr  = (const float4*)x;
    const float4* __restrict__ wr0 = (const float4*)(w + (size_t)row0 * SOM_DIM);
    const float4* __restrict__ wr1 = (const float4*)(w + (size_t)(row0 + 1) * SOM_DIM);

    float4 wv0[4], wv1[4], xv[4];
#pragma unroll
    for (int i = 0; i < 4; i++) wv0[i] = ldg_pol(&wr0[lane + 32 * i], pol);
#pragma unroll
    for (int i = 0; i < 4; i++) wv1[i] = ldg_pol(&wr1[lane + 32 * i], pol);
#pragma unroll
    for (int i = 0; i < 4; i++) xv[i]  = __ldg(&xr[lane + 32 * i]);

    float a0 = 0.f, a1 = 0.f;
#pragma unroll
    for (int i = 0; i < 4; i++) {
        float d;
        d = xv[i].x - wv0[i].x + 1e-6f; a0 += d * d;
        d = xv[i].y - wv0[i].y + 1e-6f; a0 += d * d;
        d = xv[i].z - wv0[i].z + 1e-6f; a0 += d * d;
        d = xv[i].w - wv0[i].w + 1e-6f; a0 += d * d;
        d = xv[i].x - wv1[i].x + 1e-6f; a1 += d * d;
        d = xv[i].y - wv1[i].y + 1e-6f; a1 += d * d;
        d = xv[i].z - wv1[i].z + 1e-6f; a1 += d * d;
        d = xv[i].w - wv1[i].w + 1e-6f; a1 += d * d;
    }
#pragma unroll
    for (int o = 16; o > 0; o >>= 1) {
        a0 += __shfl_xor_sync(0xFFFFFFFFu, a0, o);
        a1 += __shfl_xor_sync(0xFFFFFFFFu, a1, o);
    }

    if (lane == 0) {
        // dist >= 0 so fp32 bits are order-preserving; smaller row wins ties.
        unsigned long long k0 =
            ((unsigned long long)__float_as_uint(a0) << 32) | (unsigned)row0;
        unsigned long long k1 =
            ((unsigned long long)__float_as_uint(a1) << 32) | (unsigned)(row0 + 1);
        s_keys[warp] = min(k0, k1);
    }
    __syncthreads();
    if (threadIdx.x == 0) {
        unsigned long long k = s_keys[0];
#pragma unroll
        for (int i = 1; i < P1_WARPS; i++)
            k = min(k, s_keys[i]);
        atomicMin(&g_key, k);
    }
    __syncthreads();
    // Allow pass 2 to begin scheduling (its pre-sync loads don't depend on us).
    cudaTriggerProgrammaticLaunchCompletion();

    if (threadIdx.x == 0) {
        __threadfence();
        const unsigned t = atomicAdd(&g_ticket1, 1u);
        if (t == (unsigned)(gridDim.x - 1)) {
            g_ticket1 = 0u;
            const int bidx = (int)(g_key & 0xFFFFFFFFu);
            const int it   = *it_p;
            const float decay = expf(-(float)it / 2000.0f);   // N_ITER
            const float sig   = 128.0f * decay;               // SIGMA * decay
            g_rate   = 0.5f * decay;                          // ALPHA * decay
            g_inv2s2 = 1.0f / (2.0f * sig * sig);
            g_b0 = loc[2 * bidx];
            g_b1 = loc[2 * bidx + 1];
            if (has_idx_tail)
                out[(size_t)SOM_MN * SOM_DIM] = (float)bidx;
            __threadfence();
        }
    }
}

// ---------------------------------------------------------------------------
// Pass 2 (PDL secondary): front-load ALL p1-independent memory (W row, x,
// own loc) BEFORE cudaGridDependencySynchronize(), then read the bmu
// scalars and finish. Descending rows, tail evict-last, out stored .cs.
// Last block resets g_key for the next graph replay.
// ---------------------------------------------------------------------------
__global__ __launch_bounds__(256) void som_update_kernel(
    const float* __restrict__ x, const float* __restrict__ w,
    const float* __restrict__ loc, float* __restrict__ out)
{
    const int lane = threadIdx.x & 31;
    const int warp = threadIdx.x >> 5;
    const int row  = (SOM_MN - 1) - (blockIdx.x * P2_ROWS_PER_BLK + warp);

    const unsigned long long pol = (row >= ROW_SPLIT) ? pol_evict_last()
                                                      : pol_evict_first();

    const float4* __restrict__ xr = (const float4*)x;
    const float4* __restrict__ wr = (const float4*)(w + (size_t)row * SOM_DIM);
    float4* __restrict__ orow = (float4*)(out + (size_t)row * SOM_DIM);

    // ---- p1-independent prework: issue all streaming loads now ----
    float4 wv[4], xv[4];
#pragma unroll
    for (int i = 0; i < 4; i++) wv[i] = ldg_pol(&wr[lane + 32 * i], pol);
#pragma unroll
    for (int i = 0; i < 4; i++) xv[i] = __ldg(&xr[lane + 32 * i]);
    const float l0 = __ldg(&loc[2 * row]);
    const float l1 = __ldg(&loc[2 * row + 1]);

    // ---- wait for pass 1 grid completion (scalars + g_key visible) ----
    cudaGridDependencySynchronize();

    const float d0 = g_b0 - l0 + 1e-6f;
    const float d1 = g_b1 - l1 + 1e-6f;
    const float ld = sqrtf(d0 * d0 + d1 * d1);        // match sqrt-then-square
    const float c  = g_rate * expf(-(ld * ld) * g_inv2s2);

#pragma unroll
    for (int i = 0; i < 4; i++) {
        float4 o;
        o.x = wv[i].x + c * (xv[i].x - wv[i].x);
        o.y = wv[i].y + c * (xv[i].y - wv[i].y);
        o.z = wv[i].z + c * (xv[i].z - wv[i].z);
        o.w = wv[i].w + c * (xv[i].w - wv[i].w);
        __stcs(&orow[lane + 32 * i], o);
    }

    // Last finishing block resets g_key for the next graph replay.
    __syncthreads();
    if (threadIdx.x == 0) {
        const unsigned t = atomicAdd(&g_ticket2, 1u);
        if (t == (unsigned)(gridDim.x - 1)) {
            g_ticket2 = 0u;
            g_key = 0xFFFFFFFFFFFFFFFFULL;
            __threadfence();
        }
    }
}

extern "C" void kernel_launch(void* const* d_in, const int* in_sizes, int n_in,
                              void* d_out, int out_size)
{
    const float* x   = (const float*)d_in[0];   // (512,)
    const float* w   = (const float*)d_in[1];   // (65536, 512)
    const float* loc = (const float*)d_in[2];   // (65536, 2)
    const int*   it  = (const int*)d_in[3];     // scalar
    float* out = (float*)d_out;

    const int has_tail = (out_size > SOM_MN * SOM_DIM) ? 1 : 0;

    som_dist_kernel<<<P1_BLOCKS, 256>>>(x, w, loc, it, out, has_tail);

    // Pass 2 as a PDL secondary: may begin while pass 1 drains.
    cudaLaunchConfig_t cfg = {};
    cfg.gridDim  = dim3(P2_BLOCKS, 1, 1);
    cfg.blockDim = dim3(256, 1, 1);
    cudaLaunchAttribute attrs[1];
    attrs[0].id = cudaLaunchAttributeProgrammaticStreamSerialization;
    attrs[0].val.programmaticStreamSerializationAllowed = 1;
    cfg.attrs = attrs;
    cfg.numAttrs = 1;
    cudaLaunchKernelEx(&cfg, som_update_kernel, x, w, loc, out);
}